// round 13
// baseline (speedup 1.0000x reference)
#include <cuda_runtime.h>
#include <math.h>

#define NN 4096
#define F_IN 128
#define HH 4
#define FO 64
#define D2 256
#define VV 16
#define H1 96
#define H2 32
#define JSPLIT 8
#define JLEN (NN / JSPLIT)

// ---------------- scratch (device globals; no allocs allowed) ----------------
__device__ __align__(16) float g_p[NN * D2];       // x @ Wp1
__device__ __align__(16) float g_skip[NN * D2];    // x @ Wskip1
__device__ __align__(16) float g_out1[NN * D2];    // elu(attn-out + skip + bias1)
__device__ __align__(16) float g_p2[NN * D2];      // out1 @ Wp2
__device__ __align__(16) float g_num[NN * D2];     // attention numerator (split-K accum)
__device__ float g_Z[HH * NN];                     // softmax denominators (split-K accum)
__device__ float g_ssrc[HH * NN];
__device__ __align__(16) float g_stgt[HH * NN];
__device__ float g_E1s[HH * NN];
__device__ float g_E2s[HH * NN];
__device__ __align__(16) float g_E1t[HH * NN];
__device__ __align__(16) float g_E2t[HH * NN];
__device__ float g_ss[NN];
__device__ float g_st[NN];
__device__ float g_h1[NN * H1];                    // msw @ W1 (atomic accum)

// ---------------- zero accumulators ----------------
__global__ void zero_acc() {
    int t = blockIdx.x * blockDim.x + threadIdx.x;
    if (t < NN * D2) g_num[t] = 0.f;
    if (t < HH * NN) g_Z[t] = 0.f;
    if (t < NN * H1) g_h1[t] = 0.f;
}

// ---------------- fused dual SGEMM: g_p = x@Wp1, g_skip = x@Wsk ----------------
__global__ void __launch_bounds__(256) xgemm_dual(const float* __restrict__ x,
                                                  const float* __restrict__ Wp1,
                                                  const float* __restrict__ Wsk) {
    __shared__ float As[16][64];
    __shared__ float B1s[16][64];
    __shared__ float B2s[16][64];
    int t = threadIdx.x;
    int tx = t & 15, ty = t >> 4;
    int m0 = blockIdx.y * 64, n0 = blockIdx.x * 64;
    float acc1[4][4] = {};
    float acc2[4][4] = {};
    for (int k0 = 0; k0 < F_IN; k0 += 16) {
#pragma unroll
        for (int i = 0; i < 4; i++) {
            int lin = t + i * 256;
            int m = lin >> 4, k = lin & 15;
            As[k][m] = x[(size_t)(m0 + m) * F_IN + k0 + k];
        }
#pragma unroll
        for (int i = 0; i < 4; i++) {
            int lin = t + i * 256;
            int k = lin >> 6, n = lin & 63;
            B1s[k][n] = Wp1[(size_t)(k0 + k) * D2 + n0 + n];
            B2s[k][n] = Wsk[(size_t)(k0 + k) * D2 + n0 + n];
        }
        __syncthreads();
#pragma unroll
        for (int k = 0; k < 16; k++) {
            float a[4], b1[4], b2[4];
#pragma unroll
            for (int r = 0; r < 4; r++) a[r] = As[k][ty * 4 + r];
#pragma unroll
            for (int c = 0; c < 4; c++) { b1[c] = B1s[k][tx * 4 + c]; b2[c] = B2s[k][tx * 4 + c]; }
#pragma unroll
            for (int r = 0; r < 4; r++)
#pragma unroll
                for (int c = 0; c < 4; c++) {
                    acc1[r][c] = fmaf(a[r], b1[c], acc1[r][c]);
                    acc2[r][c] = fmaf(a[r], b2[c], acc2[r][c]);
                }
        }
        __syncthreads();
    }
#pragma unroll
    for (int r = 0; r < 4; r++)
#pragma unroll
        for (int c = 0; c < 4; c++) {
            size_t idx = (size_t)(m0 + ty * 4 + r) * D2 + n0 + tx * 4 + c;
            g_p[idx] = acc1[r][c];
            g_skip[idx] = acc2[r][c];
        }
}

// ---------------- SGEMM: g_p2 = g_out1 @ Wp2 (4096x256 @ 256x256) ----------------
__global__ void __launch_bounds__(256) p2gemm(const float* __restrict__ Wp2) {
    __shared__ float As[16][64];
    __shared__ float Bs[16][64];
    int t = threadIdx.x;
    int tx = t & 15, ty = t >> 4;
    int m0 = blockIdx.y * 64, n0 = blockIdx.x * 64;
    float acc[4][4] = {};
    for (int k0 = 0; k0 < D2; k0 += 16) {
#pragma unroll
        for (int i = 0; i < 4; i++) {
            int lin = t + i * 256;
            int m = lin >> 4, k = lin & 15;
            As[k][m] = g_out1[(size_t)(m0 + m) * D2 + k0 + k];
        }
#pragma unroll
        for (int i = 0; i < 4; i++) {
            int lin = t + i * 256;
            int k = lin >> 6, n = lin & 63;
            Bs[k][n] = Wp2[(size_t)(k0 + k) * D2 + n0 + n];
        }
        __syncthreads();
#pragma unroll
        for (int k = 0; k < 16; k++) {
            float a[4], b[4];
#pragma unroll
            for (int r = 0; r < 4; r++) a[r] = As[k][ty * 4 + r];
#pragma unroll
            for (int c = 0; c < 4; c++) b[c] = Bs[k][tx * 4 + c];
#pragma unroll
            for (int r = 0; r < 4; r++)
#pragma unroll
                for (int c = 0; c < 4; c++) acc[r][c] = fmaf(a[r], b[c], acc[r][c]);
        }
        __syncthreads();
    }
#pragma unroll
    for (int r = 0; r < 4; r++)
#pragma unroll
        for (int c = 0; c < 4; c++)
            g_p2[(size_t)(m0 + ty * 4 + r) * D2 + n0 + tx * 4 + c] = acc[r][c];
}

// ---------------- per-node GAT scores + exp factor tables ----------------
__global__ void node_scores(const float* __restrict__ a_src,
                            const float* __restrict__ a_tgt) {
    int t = blockIdx.x * blockDim.x + threadIdx.x;
    if (t >= NN * HH) return;
    int n = t >> 2, h = t & 3;
    const float* pr = g_p + (size_t)n * D2 + h * FO;
    float ss = 0.f, st = 0.f;
#pragma unroll 8
    for (int f = 0; f < FO; f++) {
        float pv = pr[f];
        ss = fmaf(pv, a_src[h * FO + f], ss);
        st = fmaf(pv, a_tgt[h * FO + f], st);
    }
    int idx = h * NN + n;
    g_ssrc[idx] = ss;
    g_stgt[idx] = st;
    g_E1s[idx] = expf(ss);
    g_E2s[idx] = expf(0.2f * ss);
    g_E1t[idx] = expf(st);
    g_E2t[idx] = expf(0.2f * st);
}

// ---------------- split-K fused GAT attention (v3: 64-row blocks, 8 rows/warp) --
// Block: 64 i-rows x 256 cols; j-tiles of 32; 2 barriers per tile.
// Lane owns cols [lane*4,+4) (head lane>>4) and [128+lane*4,+4) (head +2).
__global__ void __launch_bounds__(256) attn_split(const float* __restrict__ sw) {
    __shared__ __align__(16) float Psh[32][256];       // 32 KB
    __shared__ __align__(16) float Wts[4 * 2056];      // [h][i(64)][j(32)], plane stride 2056
    __shared__ float ss_sh[4][64], E1s_sh[4][64], E2s_sh[4][64];
    __shared__ float Zsh[64][4];

    int t = threadIdx.x;
    int i0 = blockIdx.x * 64;
    int jbase = blockIdx.y * JLEN;

    {
        int h = t >> 6, i = t & 63;
        int idx = h * NN + i0 + i;
        ss_sh[h][i] = g_ssrc[idx];
        E1s_sh[h][i] = g_E1s[idx];
        E2s_sh[h][i] = g_E2s[idx];
        Zsh[t >> 2][t & 3] = 0.f;
    }

    int w = t >> 5, lane = t & 31;
    int r0 = w * 8;            // 8 i-rows per warp
    int hA = lane >> 4;        // head for cols [cA, cA+4)
    int hB = hA + 2;           // head for cols [128+cA, ...)
    int cA = lane * 4;
    int wi = t >> 2;           // builder: i-row 0..63
    int jj = (t & 3) * 8;      // builder: j offset 0..24 (handles jj and jj+4)
    int prow = t >> 6;         // P loader
    int pcol = (t & 63) * 4;

    const float* swrow = sw + (size_t)(i0 + wi) * NN;
    float4 sw0 = *(const float4*)&swrow[jbase + jj];
    float4 sw1 = *(const float4*)&swrow[jbase + jj + 4];

    float zpart[4] = {0.f, 0.f, 0.f, 0.f};
    float accA[8][4] = {};
    float accB[8][4] = {};

    for (int j0 = jbase; j0 < jbase + JLEN; j0 += 32) {
        __syncthreads();   // Psh/Wts consumable again

        // load P tile (conflict-free float4)
#pragma unroll
        for (int rr = 0; rr < 8; rr++) {
            int row = rr * 4 + prow;
            *(float4*)&Psh[row][pcol] =
                *(const float4*)&g_p[(size_t)(j0 + row) * D2 + pcol];
        }

        // build weight tile w[h][i][j] (tables from gmem — L1-hot after tile 0)
#pragma unroll
        for (int h = 0; h < 4; h++) {
            float ssi = ss_sh[h][wi];
            float e1s = E1s_sh[h][wi];
            float e2s = E2s_sh[h][wi];
            int gj = h * NN + j0 + jj;
            float4 st0 = *(const float4*)&g_stgt[gj];
            float4 a0  = *(const float4*)&g_E1t[gj];
            float4 b0  = *(const float4*)&g_E2t[gj];
            float4 st1 = *(const float4*)&g_stgt[gj + 4];
            float4 a1  = *(const float4*)&g_E1t[gj + 4];
            float4 b1  = *(const float4*)&g_E2t[gj + 4];
            float4 w0, w1;
            w0.x = (sw0.x > 0.f) ? ((ssi + st0.x > 0.f) ? e1s * a0.x : e2s * b0.x) : 0.f;
            w0.y = (sw0.y > 0.f) ? ((ssi + st0.y > 0.f) ? e1s * a0.y : e2s * b0.y) : 0.f;
            w0.z = (sw0.z > 0.f) ? ((ssi + st0.z > 0.f) ? e1s * a0.z : e2s * b0.z) : 0.f;
            w0.w = (sw0.w > 0.f) ? ((ssi + st0.w > 0.f) ? e1s * a0.w : e2s * b0.w) : 0.f;
            w1.x = (sw1.x > 0.f) ? ((ssi + st1.x > 0.f) ? e1s * a1.x : e2s * b1.x) : 0.f;
            w1.y = (sw1.y > 0.f) ? ((ssi + st1.y > 0.f) ? e1s * a1.y : e2s * b1.y) : 0.f;
            w1.z = (sw1.z > 0.f) ? ((ssi + st1.z > 0.f) ? e1s * a1.z : e2s * b1.z) : 0.f;
            w1.w = (sw1.w > 0.f) ? ((ssi + st1.w > 0.f) ? e1s * a1.w : e2s * b1.w) : 0.f;
            zpart[h] += ((w0.x + w0.y) + (w0.z + w0.w)) + ((w1.x + w1.y) + (w1.z + w1.w));
            *(float4*)&Wts[h * 2056 + wi * 32 + jj] = w0;
            *(float4*)&Wts[h * 2056 + wi * 32 + jj + 4] = w1;
        }
        __syncthreads();   // tile ready

        // prefetch next tile's sw (hidden under the FMA phase)
        {
            int jn = j0 + 32;
            if (jn >= jbase + JLEN) jn = jbase;   // harmless dummy on last tile
            sw0 = *(const float4*)&swrow[jn + jj];
            sw1 = *(const float4*)&swrow[jn + jj + 4];
        }

        // FMA over the 32-j tile; P float4s reused across all 8 rows
#pragma unroll
        for (int k = 0; k < 32; k += 4) {
            {
                float4 p0 = *(const float4*)&Psh[k][cA];
                float4 p1 = *(const float4*)&Psh[k + 1][cA];
                float4 p2 = *(const float4*)&Psh[k + 2][cA];
                float4 p3 = *(const float4*)&Psh[k + 3][cA];
#pragma unroll
                for (int r = 0; r < 8; r++) {
                    float4 wq = *(const float4*)&Wts[hA * 2056 + (r0 + r) * 32 + k];
                    accA[r][0] = fmaf(wq.x, p0.x, accA[r][0]);
                    accA[r][1] = fmaf(wq.x, p0.y, accA[r][1]);
                    accA[r][2] = fmaf(wq.x, p0.z, accA[r][2]);
                    accA[r][3] = fmaf(wq.x, p0.w, accA[r][3]);
                    accA[r][0] = fmaf(wq.y, p1.x, accA[r][0]);
                    accA[r][1] = fmaf(wq.y, p1.y, accA[r][1]);
                    accA[r][2] = fmaf(wq.y, p1.z, accA[r][2]);
                    accA[r][3] = fmaf(wq.y, p1.w, accA[r][3]);
                    accA[r][0] = fmaf(wq.z, p2.x, accA[r][0]);
                    accA[r][1] = fmaf(wq.z, p2.y, accA[r][1]);
                    accA[r][2] = fmaf(wq.z, p2.z, accA[r][2]);
                    accA[r][3] = fmaf(wq.z, p2.w, accA[r][3]);
                    accA[r][0] = fmaf(wq.w, p3.x, accA[r][0]);
                    accA[r][1] = fmaf(wq.w, p3.y, accA[r][1]);
                    accA[r][2] = fmaf(wq.w, p3.z, accA[r][2]);
                    accA[r][3] = fmaf(wq.w, p3.w, accA[r][3]);
                }
            }
            {
                float4 p0 = *(const float4*)&Psh[k][128 + cA];
                float4 p1 = *(const float4*)&Psh[k + 1][128 + cA];
                float4 p2 = *(const float4*)&Psh[k + 2][128 + cA];
                float4 p3 = *(const float4*)&Psh[k + 3][128 + cA];
#pragma unroll
                for (int r = 0; r < 8; r++) {
                    float4 wq = *(const float4*)&Wts[hB * 2056 + (r0 + r) * 32 + k];
                    accB[r][0] = fmaf(wq.x, p0.x, accB[r][0]);
                    accB[r][1] = fmaf(wq.x, p0.y, accB[r][1]);
                    accB[r][2] = fmaf(wq.x, p0.z, accB[r][2]);
                    accB[r][3] = fmaf(wq.x, p0.w, accB[r][3]);
                    accB[r][0] = fmaf(wq.y, p1.x, accB[r][0]);
                    accB[r][1] = fmaf(wq.y, p1.y, accB[r][1]);
                    accB[r][2] = fmaf(wq.y, p1.z, accB[r][2]);
                    accB[r][3] = fmaf(wq.y, p1.w, accB[r][3]);
                    accB[r][0] = fmaf(wq.z, p2.x, accB[r][0]);
                    accB[r][1] = fmaf(wq.z, p2.y, accB[r][1]);
                    accB[r][2] = fmaf(wq.z, p2.z, accB[r][2]);
                    accB[r][3] = fmaf(wq.z, p2.w, accB[r][3]);
                    accB[r][0] = fmaf(wq.w, p3.x, accB[r][0]);
                    accB[r][1] = fmaf(wq.w, p3.y, accB[r][1]);
                    accB[r][2] = fmaf(wq.w, p3.z, accB[r][2]);
                    accB[r][3] = fmaf(wq.w, p3.w, accB[r][3]);
                }
            }
        }
    }
    __syncthreads();

    // Z reduction
#pragma unroll
    for (int h = 0; h < 4; h++) atomicAdd(&Zsh[wi][h], zpart[h]);
    __syncthreads();
    {
        int i = t >> 2, h = t & 3;
        atomicAdd(&g_Z[h * NN + i0 + i], Zsh[i][h]);
    }
#pragma unroll
    for (int r = 0; r < 8; r++) {
        size_t base = (size_t)(i0 + r0 + r) * D2;
#pragma unroll
        for (int c = 0; c < 4; c++) {
            atomicAdd(&g_num[base + cA + c], accA[r][c]);
            atomicAdd(&g_num[base + 128 + cA + c], accB[r][c]);
        }
    }
}

// ---------------- finalize: out1 = elu(num/Z + skip + bias1) ----------------
__global__ void attn_finalize(const float* __restrict__ bias1) {
    int t = blockIdx.x * blockDim.x + threadIdx.x;
    if (t >= NN * D2) return;
    int i = t >> 8, c = t & 255;
    int h = c >> 6;
    float v = g_num[t] / g_Z[h * NN + i] + g_skip[t] + bias1[c];
    g_out1[t] = (v > 0.f) ? v : expm1f(v);
}

// ---------------- GATW scores ----------------
__global__ void gatw_scores(const float* __restrict__ a_src2,
                            const float* __restrict__ a_tgt2) {
    int n = blockIdx.x * blockDim.x + threadIdx.x;
    if (n >= NN) return;
    float ss = 0.f, st = 0.f;
    const float* row = g_p2 + (size_t)n * D2;
#pragma unroll 8
    for (int c = 0; c < D2; c++) {
        float v = row[c];
        ss = fmaf(v, a_src2[c], ss);
        st = fmaf(v, a_tgt2[c], st);
    }
    g_ss[n] = ss;
    g_st[n] = st;
}

// ---------------- fused msw + (msw @ W1) with split-K atomics ----------------
__global__ void __launch_bounds__(256) msw_h1(const float* __restrict__ sw,
                                              const float* __restrict__ W1,
                                              float* __restrict__ msw_out) {
    __shared__ float ss_sh[32];
    __shared__ float st_sh[16];
    __shared__ float W1t[16][96];
    __shared__ float mt[32][16];

    int t = threadIdx.x;
    int i0 = blockIdx.y * 32;
    int jbase = blockIdx.x * 512;
    if (t < 32) ss_sh[t] = g_ss[i0 + t];

    int tx = t & 31, ty = t >> 5;
    float acc[4][3] = {};

    for (int j0 = jbase; j0 < jbase + 512; j0 += 16) {
        __syncthreads();
        if (t < 16) st_sh[t] = g_st[j0 + t];
#pragma unroll
        for (int i = 0; i < 6; i++) {
            int lin = t + i * 256;
            int k = lin / 96, c = lin % 96;
            W1t[k][c] = W1[(size_t)(j0 + k) * H1 + c];
        }
        __syncthreads();
#pragma unroll
        for (int e = 0; e < 2; e++) {
            int lin = t + e * 256;
            int i = lin >> 4, jj = lin & 15;
            float nas = ss_sh[i] + st_sh[jj];
            nas = nas > 0.f ? nas : 0.f;
            float m = nas * sw[(size_t)(i0 + i) * NN + j0 + jj];
            mt[i][jj] = m;
            msw_out[(size_t)(i0 + i) * NN + j0 + jj] = m;
        }
        __syncthreads();
#pragma unroll
        for (int k = 0; k < 16; k++) {
            float mr[4];
#pragma unroll
            for (int r = 0; r < 4; r++) mr[r] = mt[ty * 4 + r][k];
            float wv[3];
#pragma unroll
            for (int c = 0; c < 3; c++) wv[c] = W1t[k][tx * 3 + c];
#pragma unroll
            for (int r = 0; r < 4; r++)
#pragma unroll
                for (int c = 0; c < 3; c++) acc[r][c] = fmaf(mr[r], wv[c], acc[r][c]);
        }
    }
#pragma unroll
    for (int r = 0; r < 4; r++)
#pragma unroll
        for (int c = 0; c < 3; c++)
            atomicAdd(&g_h1[(size_t)(i0 + ty * 4 + r) * H1 + tx * 3 + c], acc[r][c]);
}

// ---------------- regression head: h1 -> h2 -> beta, y_hat ----------------
__global__ void __launch_bounds__(256) head_kernel(const float* __restrict__ W2,
                                                   const float* __restrict__ b2,
                                                   const float* __restrict__ W3,
                                                   const float* __restrict__ b3,
                                                   const float* __restrict__ ols,
                                                   const float* __restrict__ vx,
                                                   const float* __restrict__ b1v,
                                                   float* __restrict__ beta_out,
                                                   float* __restrict__ yhat_out) {
    __shared__ float W2s[96][32];
    __shared__ float W3s[32][16];
    __shared__ float b2s[32], b3s[16], olss[16], b1s[96];
    int t = threadIdx.x;
    for (int i = t; i < 96 * 32; i += 256) W2s[i / 32][i % 32] = W2[i];
    for (int i = t; i < 32 * 16; i += 256) W3s[i / 16][i % 16] = W3[i];
    if (t < 32) b2s[t] = b2[t];
    if (t < 16) { b3s[t] = b3[t]; olss[t] = ols[t]; }
    if (t < 96) b1s[t] = b1v[t];
    __syncthreads();

    int n = blockIdx.x * 256 + t;
    if (n >= NN) return;

    float h2[32];
#pragma unroll
    for (int c2 = 0; c2 < 32; c2++) h2[c2] = b2s[c2];
    for (int c = 0; c < 96; c++) {
        float hv = g_h1[(size_t)n * 96 + c] + b1s[c];
#pragma unroll
        for (int c2 = 0; c2 < 32; c2++) h2[c2] = fmaf(hv, W2s[c][c2], h2[c2]);
    }
    float yh = 0.f;
#pragma unroll
    for (int v = 0; v < 16; v++) {
        float s = b3s[v];
#pragma unroll
        for (int c2 = 0; c2 < 32; c2++) s = fmaf(h2[c2], W3s[c2][v], s);
        s = (s > 0.f) ? s : 0.2f * s;
        s *= olss[v];
        beta_out[(size_t)n * 16 + v] = s;
        yh = fmaf(s, vx[(size_t)n * 16 + v], yh);
    }
    yhat_out[n] = yh;
}

// ---------------- launcher (kernel launches ONLY — graph-capture safe) --------
extern "C" void kernel_launch(void* const* d_in, const int* in_sizes, int n_in,
                              void* d_out, int out_size) {
    const float* x    = (const float*)d_in[0];
    const float* sw   = (const float*)d_in[2];
    const float* Wp1  = (const float*)d_in[3];
    const float* a_s1 = (const float*)d_in[4];
    const float* a_t1 = (const float*)d_in[5];
    const float* Wsk  = (const float*)d_in[6];
    const float* bias1= (const float*)d_in[7];
    const float* Wp2  = (const float*)d_in[8];
    const float* a_s2 = (const float*)d_in[9];
    const float* a_t2 = (const float*)d_in[10];
    const float* W1   = (const float*)d_in[11];
    const float* b1   = (const float*)d_in[12];
    const float* W2   = (const float*)d_in[13];
    const float* b2   = (const float*)d_in[14];
    const float* W3   = (const float*)d_in[15];
    const float* b3   = (const float*)d_in[16];
    const float* ols  = (const float*)d_in[17];
    const float* vx   = (const float*)d_in[18];

    float* out = (float*)d_out;
    float* beta_out = out;                       // N*V = 65536
    float* yhat_out = out + NN * VV;             // N = 4096
    float* msw_out  = out + NN * VV + NN;        // N*N

    zero_acc<<<(NN * D2 + 255) / 256, 256>>>();
    xgemm_dual<<<dim3(D2 / 64, NN / 64), 256>>>(x, Wp1, Wsk);
    node_scores<<<(NN * HH + 255) / 256, 256>>>(a_s1, a_t1);
    attn_split<<<dim3(NN / 64, JSPLIT), 256>>>(sw);
    attn_finalize<<<(NN * D2 + 255) / 256, 256>>>(bias1);
    p2gemm<<<dim3(D2 / 64, NN / 64), 256>>>(Wp2);
    gatw_scores<<<NN / 256, 256>>>(a_s2, a_t2);
    msw_h1<<<dim3(8, NN / 32), 256>>>(sw, W1, msw_out);
    head_kernel<<<NN / 256, 256>>>(W2, b2, W3, b3, ols, vx, b1, beta_out, yhat_out);
}

// round 14
// speedup vs baseline: 1.1010x; 1.1010x over previous
#include <cuda_runtime.h>
#include <math.h>

#define NN 4096
#define F_IN 128
#define HH 4
#define FO 64
#define D2 256
#define VV 16
#define H1 96
#define H2 32
#define JSPLIT 8
#define JLEN (NN / JSPLIT)

// ---------------- scratch (device globals; no allocs allowed) ----------------
__device__ __align__(16) float g_p[NN * D2];       // x @ Wp1
__device__ __align__(16) float g_skip[NN * D2];    // x @ Wskip1
__device__ __align__(16) float g_out1[NN * D2];    // elu(attn-out + skip + bias1)
__device__ __align__(16) float g_p2[NN * D2];      // out1 @ Wp2
__device__ __align__(16) float g_num[NN * D2];     // attention numerator (split-K accum)
__device__ float g_Z[HH * NN];                     // softmax denominators (split-K accum)
__device__ float g_ssrc[HH * NN];
__device__ __align__(16) float g_stgt[HH * NN];
__device__ float g_E1s[HH * NN];
__device__ float g_E2s[HH * NN];
__device__ __align__(16) float g_E1t[HH * NN];
__device__ __align__(16) float g_E2t[HH * NN];
__device__ float g_ss[NN];
__device__ float g_st[NN];
__device__ float g_h1[NN * H1];                    // msw @ W1 (atomic accum)

// ---------------- zero accumulators ----------------
__global__ void zero_acc() {
    int t = blockIdx.x * blockDim.x + threadIdx.x;
    if (t < NN * D2) g_num[t] = 0.f;
    if (t < HH * NN) g_Z[t] = 0.f;
    if (t < NN * H1) g_h1[t] = 0.f;
}

// ---------------- fused dual SGEMM: g_p = x@Wp1, g_skip = x@Wsk ----------------
__global__ void __launch_bounds__(256) xgemm_dual(const float* __restrict__ x,
                                                  const float* __restrict__ Wp1,
                                                  const float* __restrict__ Wsk) {
    __shared__ float As[16][64];
    __shared__ float B1s[16][64];
    __shared__ float B2s[16][64];
    int t = threadIdx.x;
    int tx = t & 15, ty = t >> 4;
    int m0 = blockIdx.y * 64, n0 = blockIdx.x * 64;
    float acc1[4][4] = {};
    float acc2[4][4] = {};
    for (int k0 = 0; k0 < F_IN; k0 += 16) {
#pragma unroll
        for (int i = 0; i < 4; i++) {
            int lin = t + i * 256;
            int m = lin >> 4, k = lin & 15;
            As[k][m] = x[(size_t)(m0 + m) * F_IN + k0 + k];
        }
#pragma unroll
        for (int i = 0; i < 4; i++) {
            int lin = t + i * 256;
            int k = lin >> 6, n = lin & 63;
            B1s[k][n] = Wp1[(size_t)(k0 + k) * D2 + n0 + n];
            B2s[k][n] = Wsk[(size_t)(k0 + k) * D2 + n0 + n];
        }
        __syncthreads();
#pragma unroll
        for (int k = 0; k < 16; k++) {
            float a[4], b1[4], b2[4];
#pragma unroll
            for (int r = 0; r < 4; r++) a[r] = As[k][ty * 4 + r];
#pragma unroll
            for (int c = 0; c < 4; c++) { b1[c] = B1s[k][tx * 4 + c]; b2[c] = B2s[k][tx * 4 + c]; }
#pragma unroll
            for (int r = 0; r < 4; r++)
#pragma unroll
                for (int c = 0; c < 4; c++) {
                    acc1[r][c] = fmaf(a[r], b1[c], acc1[r][c]);
                    acc2[r][c] = fmaf(a[r], b2[c], acc2[r][c]);
                }
        }
        __syncthreads();
    }
#pragma unroll
    for (int r = 0; r < 4; r++)
#pragma unroll
        for (int c = 0; c < 4; c++) {
            size_t idx = (size_t)(m0 + ty * 4 + r) * D2 + n0 + tx * 4 + c;
            g_p[idx] = acc1[r][c];
            g_skip[idx] = acc2[r][c];
        }
}

// ---------------- SGEMM: g_p2 = g_out1 @ Wp2 (4096x256 @ 256x256) ----------------
__global__ void __launch_bounds__(256) p2gemm(const float* __restrict__ Wp2) {
    __shared__ float As[16][64];
    __shared__ float Bs[16][64];
    int t = threadIdx.x;
    int tx = t & 15, ty = t >> 4;
    int m0 = blockIdx.y * 64, n0 = blockIdx.x * 64;
    float acc[4][4] = {};
    for (int k0 = 0; k0 < D2; k0 += 16) {
#pragma unroll
        for (int i = 0; i < 4; i++) {
            int lin = t + i * 256;
            int m = lin >> 4, k = lin & 15;
            As[k][m] = g_out1[(size_t)(m0 + m) * D2 + k0 + k];
        }
#pragma unroll
        for (int i = 0; i < 4; i++) {
            int lin = t + i * 256;
            int k = lin >> 6, n = lin & 63;
            Bs[k][n] = Wp2[(size_t)(k0 + k) * D2 + n0 + n];
        }
        __syncthreads();
#pragma unroll
        for (int k = 0; k < 16; k++) {
            float a[4], b[4];
#pragma unroll
            for (int r = 0; r < 4; r++) a[r] = As[k][ty * 4 + r];
#pragma unroll
            for (int c = 0; c < 4; c++) b[c] = Bs[k][tx * 4 + c];
#pragma unroll
            for (int r = 0; r < 4; r++)
#pragma unroll
                for (int c = 0; c < 4; c++) acc[r][c] = fmaf(a[r], b[c], acc[r][c]);
        }
        __syncthreads();
    }
#pragma unroll
    for (int r = 0; r < 4; r++)
#pragma unroll
        for (int c = 0; c < 4; c++)
            g_p2[(size_t)(m0 + ty * 4 + r) * D2 + n0 + tx * 4 + c] = acc[r][c];
}

// ---------------- per-node GAT scores + exp factor tables ----------------
__global__ void node_scores(const float* __restrict__ a_src,
                            const float* __restrict__ a_tgt) {
    int t = blockIdx.x * blockDim.x + threadIdx.x;
    if (t >= NN * HH) return;
    int n = t >> 2, h = t & 3;
    const float* pr = g_p + (size_t)n * D2 + h * FO;
    float ss = 0.f, st = 0.f;
#pragma unroll 8
    for (int f = 0; f < FO; f++) {
        float pv = pr[f];
        ss = fmaf(pv, a_src[h * FO + f], ss);
        st = fmaf(pv, a_tgt[h * FO + f], st);
    }
    int idx = h * NN + n;
    g_ssrc[idx] = ss;
    g_stgt[idx] = st;
    g_E1s[idx] = expf(ss);
    g_E2s[idx] = expf(0.2f * ss);
    g_E1t[idx] = expf(st);
    g_E2t[idx] = expf(0.2f * st);
}

// ---------------- split-K fused GAT attention (v3b: 64-row blocks, 2 CTAs/SM) --
// Block: 64 i-rows x 256 cols; j-tiles of 32; 2 barriers per tile.
// Lane owns cols [lane*4,+4) (head lane>>4) and [128+lane*4,+4) (head +2).
// __launch_bounds__(256,2) caps regs at 128 so 2 CTAs co-reside and overlap phases.
__global__ void __launch_bounds__(256, 2) attn_split(const float* __restrict__ sw) {
    __shared__ __align__(16) float Psh[32][256];       // 32 KB
    __shared__ __align__(16) float Wts[4 * 2056];      // [h][i(64)][j(32)], plane stride 2056
    __shared__ float ss_sh[4][64], E1s_sh[4][64], E2s_sh[4][64];
    __shared__ float Zsh[64][4];

    int t = threadIdx.x;
    int i0 = blockIdx.x * 64;
    int jbase = blockIdx.y * JLEN;

    {
        int h = t >> 6, i = t & 63;
        int idx = h * NN + i0 + i;
        ss_sh[h][i] = g_ssrc[idx];
        E1s_sh[h][i] = g_E1s[idx];
        E2s_sh[h][i] = g_E2s[idx];
        Zsh[t >> 2][t & 3] = 0.f;
    }

    int w = t >> 5, lane = t & 31;
    int r0 = w * 8;            // 8 i-rows per warp
    int hA = lane >> 4;        // head for cols [cA, cA+4)
    int hB = hA + 2;           // head for cols [128+cA, ...)
    int cA = lane * 4;
    int wi = t >> 2;           // builder: i-row 0..63
    int jj = (t & 3) * 8;      // builder: j offset 0..24 (handles jj and jj+4)
    int prow = t >> 6;         // P loader
    int pcol = (t & 63) * 4;

    const float* swrow = sw + (size_t)(i0 + wi) * NN;
    float4 sw0 = *(const float4*)&swrow[jbase + jj];
    float4 sw1 = *(const float4*)&swrow[jbase + jj + 4];

    float zpart[4] = {0.f, 0.f, 0.f, 0.f};
    float accA[8][4] = {};
    float accB[8][4] = {};

    for (int j0 = jbase; j0 < jbase + JLEN; j0 += 32) {
        __syncthreads();   // Psh/Wts consumable again

        // load P tile (conflict-free float4)
#pragma unroll
        for (int rr = 0; rr < 8; rr++) {
            int row = rr * 4 + prow;
            *(float4*)&Psh[row][pcol] =
                *(const float4*)&g_p[(size_t)(j0 + row) * D2 + pcol];
        }

        // build weight tile w[h][i][j] (tables from gmem — L1-hot after tile 0)
#pragma unroll
        for (int h = 0; h < 4; h++) {
            float ssi = ss_sh[h][wi];
            float e1s = E1s_sh[h][wi];
            float e2s = E2s_sh[h][wi];
            int gj = h * NN + j0 + jj;
            float4 st0 = *(const float4*)&g_stgt[gj];
            float4 a0  = *(const float4*)&g_E1t[gj];
            float4 b0  = *(const float4*)&g_E2t[gj];
            float4 st1 = *(const float4*)&g_stgt[gj + 4];
            float4 a1  = *(const float4*)&g_E1t[gj + 4];
            float4 b1  = *(const float4*)&g_E2t[gj + 4];
            float4 w0, w1;
            w0.x = (sw0.x > 0.f) ? ((ssi + st0.x > 0.f) ? e1s * a0.x : e2s * b0.x) : 0.f;
            w0.y = (sw0.y > 0.f) ? ((ssi + st0.y > 0.f) ? e1s * a0.y : e2s * b0.y) : 0.f;
            w0.z = (sw0.z > 0.f) ? ((ssi + st0.z > 0.f) ? e1s * a0.z : e2s * b0.z) : 0.f;
            w0.w = (sw0.w > 0.f) ? ((ssi + st0.w > 0.f) ? e1s * a0.w : e2s * b0.w) : 0.f;
            w1.x = (sw1.x > 0.f) ? ((ssi + st1.x > 0.f) ? e1s * a1.x : e2s * b1.x) : 0.f;
            w1.y = (sw1.y > 0.f) ? ((ssi + st1.y > 0.f) ? e1s * a1.y : e2s * b1.y) : 0.f;
            w1.z = (sw1.z > 0.f) ? ((ssi + st1.z > 0.f) ? e1s * a1.z : e2s * b1.z) : 0.f;
            w1.w = (sw1.w > 0.f) ? ((ssi + st1.w > 0.f) ? e1s * a1.w : e2s * b1.w) : 0.f;
            zpart[h] += ((w0.x + w0.y) + (w0.z + w0.w)) + ((w1.x + w1.y) + (w1.z + w1.w));
            *(float4*)&Wts[h * 2056 + wi * 32 + jj] = w0;
            *(float4*)&Wts[h * 2056 + wi * 32 + jj + 4] = w1;
        }
        __syncthreads();   // tile ready

        // prefetch next tile's sw (hidden under the FMA phase)
        {
            int jn = j0 + 32;
            if (jn >= jbase + JLEN) jn = jbase;   // harmless dummy on last tile
            sw0 = *(const float4*)&swrow[jn + jj];
            sw1 = *(const float4*)&swrow[jn + jj + 4];
        }

        // FMA over the 32-j tile; P float4s reused across all 8 rows
#pragma unroll
        for (int k = 0; k < 32; k += 4) {
            {
                float4 p0 = *(const float4*)&Psh[k][cA];
                float4 p1 = *(const float4*)&Psh[k + 1][cA];
                float4 p2 = *(const float4*)&Psh[k + 2][cA];
                float4 p3 = *(const float4*)&Psh[k + 3][cA];
#pragma unroll
                for (int r = 0; r < 8; r++) {
                    float4 wq = *(const float4*)&Wts[hA * 2056 + (r0 + r) * 32 + k];
                    accA[r][0] = fmaf(wq.x, p0.x, accA[r][0]);
                    accA[r][1] = fmaf(wq.x, p0.y, accA[r][1]);
                    accA[r][2] = fmaf(wq.x, p0.z, accA[r][2]);
                    accA[r][3] = fmaf(wq.x, p0.w, accA[r][3]);
                    accA[r][0] = fmaf(wq.y, p1.x, accA[r][0]);
                    accA[r][1] = fmaf(wq.y, p1.y, accA[r][1]);
                    accA[r][2] = fmaf(wq.y, p1.z, accA[r][2]);
                    accA[r][3] = fmaf(wq.y, p1.w, accA[r][3]);
                    accA[r][0] = fmaf(wq.z, p2.x, accA[r][0]);
                    accA[r][1] = fmaf(wq.z, p2.y, accA[r][1]);
                    accA[r][2] = fmaf(wq.z, p2.z, accA[r][2]);
                    accA[r][3] = fmaf(wq.z, p2.w, accA[r][3]);
                    accA[r][0] = fmaf(wq.w, p3.x, accA[r][0]);
                    accA[r][1] = fmaf(wq.w, p3.y, accA[r][1]);
                    accA[r][2] = fmaf(wq.w, p3.z, accA[r][2]);
                    accA[r][3] = fmaf(wq.w, p3.w, accA[r][3]);
                }
            }
            {
                float4 p0 = *(const float4*)&Psh[k][128 + cA];
                float4 p1 = *(const float4*)&Psh[k + 1][128 + cA];
                float4 p2 = *(const float4*)&Psh[k + 2][128 + cA];
                float4 p3 = *(const float4*)&Psh[k + 3][128 + cA];
#pragma unroll
                for (int r = 0; r < 8; r++) {
                    float4 wq = *(const float4*)&Wts[hB * 2056 + (r0 + r) * 32 + k];
                    accB[r][0] = fmaf(wq.x, p0.x, accB[r][0]);
                    accB[r][1] = fmaf(wq.x, p0.y, accB[r][1]);
                    accB[r][2] = fmaf(wq.x, p0.z, accB[r][2]);
                    accB[r][3] = fmaf(wq.x, p0.w, accB[r][3]);
                    accB[r][0] = fmaf(wq.y, p1.x, accB[r][0]);
                    accB[r][1] = fmaf(wq.y, p1.y, accB[r][1]);
                    accB[r][2] = fmaf(wq.y, p1.z, accB[r][2]);
                    accB[r][3] = fmaf(wq.y, p1.w, accB[r][3]);
                    accB[r][0] = fmaf(wq.z, p2.x, accB[r][0]);
                    accB[r][1] = fmaf(wq.z, p2.y, accB[r][1]);
                    accB[r][2] = fmaf(wq.z, p2.z, accB[r][2]);
                    accB[r][3] = fmaf(wq.z, p2.w, accB[r][3]);
                    accB[r][0] = fmaf(wq.w, p3.x, accB[r][0]);
                    accB[r][1] = fmaf(wq.w, p3.y, accB[r][1]);
                    accB[r][2] = fmaf(wq.w, p3.z, accB[r][2]);
                    accB[r][3] = fmaf(wq.w, p3.w, accB[r][3]);
                }
            }
        }
    }
    __syncthreads();

    // Z reduction
#pragma unroll
    for (int h = 0; h < 4; h++) atomicAdd(&Zsh[wi][h], zpart[h]);
    __syncthreads();
    {
        int i = t >> 2, h = t & 3;
        atomicAdd(&g_Z[h * NN + i0 + i], Zsh[i][h]);
    }
#pragma unroll
    for (int r = 0; r < 8; r++) {
        size_t base = (size_t)(i0 + r0 + r) * D2;
#pragma unroll
        for (int c = 0; c < 4; c++) {
            atomicAdd(&g_num[base + cA + c], accA[r][c]);
            atomicAdd(&g_num[base + 128 + cA + c], accB[r][c]);
        }
    }
}

// ---------------- finalize: out1 = elu(num/Z + skip + bias1) ----------------
__global__ void attn_finalize(const float* __restrict__ bias1) {
    int t = blockIdx.x * blockDim.x + threadIdx.x;
    if (t >= NN * D2) return;
    int i = t >> 8, c = t & 255;
    int h = c >> 6;
    float v = g_num[t] / g_Z[h * NN + i] + g_skip[t] + bias1[c];
    g_out1[t] = (v > 0.f) ? v : expm1f(v);
}

// ---------------- GATW scores ----------------
__global__ void gatw_scores(const float* __restrict__ a_src2,
                            const float* __restrict__ a_tgt2) {
    int n = blockIdx.x * blockDim.x + threadIdx.x;
    if (n >= NN) return;
    float ss = 0.f, st = 0.f;
    const float* row = g_p2 + (size_t)n * D2;
#pragma unroll 8
    for (int c = 0; c < D2; c++) {
        float v = row[c];
        ss = fmaf(v, a_src2[c], ss);
        st = fmaf(v, a_tgt2[c], st);
    }
    g_ss[n] = ss;
    g_st[n] = st;
}

// ---------------- fused msw + (msw @ W1) with split-K atomics ----------------
__global__ void __launch_bounds__(256) msw_h1(const float* __restrict__ sw,
                                              const float* __restrict__ W1,
                                              float* __restrict__ msw_out) {
    __shared__ float ss_sh[32];
    __shared__ float st_sh[16];
    __shared__ float W1t[16][96];
    __shared__ float mt[32][16];

    int t = threadIdx.x;
    int i0 = blockIdx.y * 32;
    int jbase = blockIdx.x * 512;
    if (t < 32) ss_sh[t] = g_ss[i0 + t];

    int tx = t & 31, ty = t >> 5;
    float acc[4][3] = {};

    for (int j0 = jbase; j0 < jbase + 512; j0 += 16) {
        __syncthreads();
        if (t < 16) st_sh[t] = g_st[j0 + t];
#pragma unroll
        for (int i = 0; i < 6; i++) {
            int lin = t + i * 256;
            int k = lin / 96, c = lin % 96;
            W1t[k][c] = W1[(size_t)(j0 + k) * H1 + c];
        }
        __syncthreads();
#pragma unroll
        for (int e = 0; e < 2; e++) {
            int lin = t + e * 256;
            int i = lin >> 4, jj = lin & 15;
            float nas = ss_sh[i] + st_sh[jj];
            nas = nas > 0.f ? nas : 0.f;
            float m = nas * sw[(size_t)(i0 + i) * NN + j0 + jj];
            mt[i][jj] = m;
            msw_out[(size_t)(i0 + i) * NN + j0 + jj] = m;
        }
        __syncthreads();
#pragma unroll
        for (int k = 0; k < 16; k++) {
            float mr[4];
#pragma unroll
            for (int r = 0; r < 4; r++) mr[r] = mt[ty * 4 + r][k];
            float wv[3];
#pragma unroll
            for (int c = 0; c < 3; c++) wv[c] = W1t[k][tx * 3 + c];
#pragma unroll
            for (int r = 0; r < 4; r++)
#pragma unroll
                for (int c = 0; c < 3; c++) acc[r][c] = fmaf(mr[r], wv[c], acc[r][c]);
        }
    }
#pragma unroll
    for (int r = 0; r < 4; r++)
#pragma unroll
        for (int c = 0; c < 3; c++)
            atomicAdd(&g_h1[(size_t)(i0 + ty * 4 + r) * H1 + tx * 3 + c], acc[r][c]);
}

// ---------------- regression head: h1 -> h2 -> beta, y_hat ----------------
__global__ void __launch_bounds__(256) head_kernel(const float* __restrict__ W2,
                                                   const float* __restrict__ b2,
                                                   const float* __restrict__ W3,
                                                   const float* __restrict__ b3,
                                                   const float* __restrict__ ols,
                                                   const float* __restrict__ vx,
                                                   const float* __restrict__ b1v,
                                                   float* __restrict__ beta_out,
                                                   float* __restrict__ yhat_out) {
    __shared__ float W2s[96][32];
    __shared__ float W3s[32][16];
    __shared__ float b2s[32], b3s[16], olss[16], b1s[96];
    int t = threadIdx.x;
    for (int i = t; i < 96 * 32; i += 256) W2s[i / 32][i % 32] = W2[i];
    for (int i = t; i < 32 * 16; i += 256) W3s[i / 16][i % 16] = W3[i];
    if (t < 32) b2s[t] = b2[t];
    if (t < 16) { b3s[t] = b3[t]; olss[t] = ols[t]; }
    if (t < 96) b1s[t] = b1v[t];
    __syncthreads();

    int n = blockIdx.x * 256 + t;
    if (n >= NN) return;

    float h2[32];
#pragma unroll
    for (int c2 = 0; c2 < 32; c2++) h2[c2] = b2s[c2];
    for (int c = 0; c < 96; c++) {
        float hv = g_h1[(size_t)n * 96 + c] + b1s[c];
#pragma unroll
        for (int c2 = 0; c2 < 32; c2++) h2[c2] = fmaf(hv, W2s[c][c2], h2[c2]);
    }
    float yh = 0.f;
#pragma unroll
    for (int v = 0; v < 16; v++) {
        float s = b3s[v];
#pragma unroll
        for (int c2 = 0; c2 < 32; c2++) s = fmaf(h2[c2], W3s[c2][v], s);
        s = (s > 0.f) ? s : 0.2f * s;
        s *= olss[v];
        beta_out[(size_t)n * 16 + v] = s;
        yh = fmaf(s, vx[(size_t)n * 16 + v], yh);
    }
    yhat_out[n] = yh;
}

// ---------------- launcher (kernel launches ONLY — graph-capture safe) --------
extern "C" void kernel_launch(void* const* d_in, const int* in_sizes, int n_in,
                              void* d_out, int out_size) {
    const float* x    = (const float*)d_in[0];
    const float* sw   = (const float*)d_in[2];
    const float* Wp1  = (const float*)d_in[3];
    const float* a_s1 = (const float*)d_in[4];
    const float* a_t1 = (const float*)d_in[5];
    const float* Wsk  = (const float*)d_in[6];
    const float* bias1= (const float*)d_in[7];
    const float* Wp2  = (const float*)d_in[8];
    const float* a_s2 = (const float*)d_in[9];
    const float* a_t2 = (const float*)d_in[10];
    const float* W1   = (const float*)d_in[11];
    const float* b1   = (const float*)d_in[12];
    const float* W2   = (const float*)d_in[13];
    const float* b2   = (const float*)d_in[14];
    const float* W3   = (const float*)d_in[15];
    const float* b3   = (const float*)d_in[16];
    const float* ols  = (const float*)d_in[17];
    const float* vx   = (const float*)d_in[18];

    float* out = (float*)d_out;
    float* beta_out = out;                       // N*V = 65536
    float* yhat_out = out + NN * VV;             // N = 4096
    float* msw_out  = out + NN * VV + NN;        // N*N

    zero_acc<<<(NN * D2 + 255) / 256, 256>>>();
    xgemm_dual<<<dim3(D2 / 64, NN / 64), 256>>>(x, Wp1, Wsk);
    node_scores<<<(NN * HH + 255) / 256, 256>>>(a_s1, a_t1);
    attn_split<<<dim3(NN / 64, JSPLIT), 256>>>(sw);
    attn_finalize<<<(NN * D2 + 255) / 256, 256>>>(bias1);
    p2gemm<<<dim3(D2 / 64, NN / 64), 256>>>(Wp2);
    gatw_scores<<<NN / 256, 256>>>(a_s2, a_t2);
    msw_h1<<<dim3(8, NN / 32), 256>>>(sw, W1, msw_out);
    head_kernel<<<NN / 256, 256>>>(W2, b2, W3, b3, ols, vx, b1, beta_out, yhat_out);
}

// round 17
// speedup vs baseline: 1.1275x; 1.0241x over previous
#include <cuda_runtime.h>
#include <math.h>

#define NN 4096
#define F_IN 128
#define HH 4
#define FO 64
#define D2 256
#define VV 16
#define H1 96
#define H2 32
#define JSPLIT 8
#define JLEN (NN / JSPLIT)

// Wts2 transposed layout: [h][j(32)][i(64)]
#define ISTR 68
#define PLANE (32 * ISTR + 8)   // 2184, plane stagger = 8 banks

typedef unsigned long long u64t;

__device__ __forceinline__ u64t dup_f2(float x) {
    u64t r; asm("mov.b64 %0, {%1, %1};" : "=l"(r) : "f"(x)); return r;
}
__device__ __forceinline__ void fma2(u64t& d, u64t a, u64t b) {
    asm("fma.rn.f32x2 %0, %1, %2, %0;" : "+l"(d) : "l"(a), "l"(b));
}
__device__ __forceinline__ void unpack_f2(u64t v, float& lo, float& hi) {
    asm("mov.b64 {%0, %1}, %2;" : "=f"(lo), "=f"(hi) : "l"(v));
}

// ---------------- scratch (device globals; no allocs allowed) ----------------
__device__ __align__(16) float g_p[NN * D2];       // x @ Wp1
__device__ __align__(16) float g_skip[NN * D2];    // x @ Wskip1
__device__ __align__(16) float g_out1[NN * D2];    // elu(attn-out + skip + bias1)
__device__ __align__(16) float g_p2[NN * D2];      // out1 @ Wp2
__device__ __align__(16) float g_num[NN * D2];     // attention numerator (split-K accum)
__device__ float g_Z[HH * NN];                     // softmax denominators (split-K accum)
__device__ float g_ssrc[HH * NN];
__device__ __align__(16) float g_stgt[HH * NN];
__device__ float g_E1s[HH * NN];
__device__ float g_E2s[HH * NN];
__device__ __align__(16) float g_E1t[HH * NN];
__device__ __align__(16) float g_E2t[HH * NN];
__device__ float g_ss[NN];
__device__ __align__(16) float g_st[NN];
__device__ float g_h1[NN * H1];                    // msw @ W1 (atomic accum)

// ---------------- zero accumulators ----------------
__global__ void zero_acc() {
    int t = blockIdx.x * blockDim.x + threadIdx.x;
    if (t < NN * D2) g_num[t] = 0.f;
    if (t < HH * NN) g_Z[t] = 0.f;
    if (t < NN * H1) g_h1[t] = 0.f;
}

// ---------------- fused dual SGEMM: g_p = x@Wp1, g_skip = x@Wsk ----------------
__global__ void __launch_bounds__(256) xgemm_dual(const float* __restrict__ x,
                                                  const float* __restrict__ Wp1,
                                                  const float* __restrict__ Wsk) {
    __shared__ float As[16][64];
    __shared__ float B1s[16][64];
    __shared__ float B2s[16][64];
    int t = threadIdx.x;
    int tx = t & 15, ty = t >> 4;
    int m0 = blockIdx.y * 64, n0 = blockIdx.x * 64;
    float acc1[4][4] = {};
    float acc2[4][4] = {};
    for (int k0 = 0; k0 < F_IN; k0 += 16) {
#pragma unroll
        for (int i = 0; i < 4; i++) {
            int lin = t + i * 256;
            int m = lin >> 4, k = lin & 15;
            As[k][m] = x[(size_t)(m0 + m) * F_IN + k0 + k];
        }
#pragma unroll
        for (int i = 0; i < 4; i++) {
            int lin = t + i * 256;
            int k = lin >> 6, n = lin & 63;
            B1s[k][n] = Wp1[(size_t)(k0 + k) * D2 + n0 + n];
            B2s[k][n] = Wsk[(size_t)(k0 + k) * D2 + n0 + n];
        }
        __syncthreads();
#pragma unroll
        for (int k = 0; k < 16; k++) {
            float a[4], b1[4], b2[4];
#pragma unroll
            for (int r = 0; r < 4; r++) a[r] = As[k][ty * 4 + r];
#pragma unroll
            for (int c = 0; c < 4; c++) { b1[c] = B1s[k][tx * 4 + c]; b2[c] = B2s[k][tx * 4 + c]; }
#pragma unroll
            for (int r = 0; r < 4; r++)
#pragma unroll
                for (int c = 0; c < 4; c++) {
                    acc1[r][c] = fmaf(a[r], b1[c], acc1[r][c]);
                    acc2[r][c] = fmaf(a[r], b2[c], acc2[r][c]);
                }
        }
        __syncthreads();
    }
#pragma unroll
    for (int r = 0; r < 4; r++)
#pragma unroll
        for (int c = 0; c < 4; c++) {
            size_t idx = (size_t)(m0 + ty * 4 + r) * D2 + n0 + tx * 4 + c;
            g_p[idx] = acc1[r][c];
            g_skip[idx] = acc2[r][c];
        }
}

// ---------------- SGEMM: g_p2 = g_out1 @ Wp2 (4096x256 @ 256x256) ----------------
__global__ void __launch_bounds__(256) p2gemm(const float* __restrict__ Wp2) {
    __shared__ float As[16][64];
    __shared__ float Bs[16][64];
    int t = threadIdx.x;
    int tx = t & 15, ty = t >> 4;
    int m0 = blockIdx.y * 64, n0 = blockIdx.x * 64;
    float acc[4][4] = {};
    for (int k0 = 0; k0 < D2; k0 += 16) {
#pragma unroll
        for (int i = 0; i < 4; i++) {
            int lin = t + i * 256;
            int m = lin >> 4, k = lin & 15;
            As[k][m] = g_out1[(size_t)(m0 + m) * D2 + k0 + k];
        }
#pragma unroll
        for (int i = 0; i < 4; i++) {
            int lin = t + i * 256;
            int k = lin >> 6, n = lin & 63;
            Bs[k][n] = Wp2[(size_t)(k0 + k) * D2 + n0 + n];
        }
        __syncthreads();
#pragma unroll
        for (int k = 0; k < 16; k++) {
            float a[4], b[4];
#pragma unroll
            for (int r = 0; r < 4; r++) a[r] = As[k][ty * 4 + r];
#pragma unroll
            for (int c = 0; c < 4; c++) b[c] = Bs[k][tx * 4 + c];
#pragma unroll
            for (int r = 0; r < 4; r++)
#pragma unroll
                for (int c = 0; c < 4; c++) acc[r][c] = fmaf(a[r], b[c], acc[r][c]);
        }
        __syncthreads();
    }
#pragma unroll
    for (int r = 0; r < 4; r++)
#pragma unroll
        for (int c = 0; c < 4; c++)
            g_p2[(size_t)(m0 + ty * 4 + r) * D2 + n0 + tx * 4 + c] = acc[r][c];
}

// ---------------- per-node GAT scores + exp factor tables ----------------
__global__ void node_scores(const float* __restrict__ a_src,
                            const float* __restrict__ a_tgt) {
    int t = blockIdx.x * blockDim.x + threadIdx.x;
    if (t >= NN * HH) return;
    int n = t >> 2, h = t & 3;
    const float* pr = g_p + (size_t)n * D2 + h * FO;
    float ss = 0.f, st = 0.f;
#pragma unroll 8
    for (int f = 0; f < FO; f++) {
        float pv = pr[f];
        ss = fmaf(pv, a_src[h * FO + f], ss);
        st = fmaf(pv, a_tgt[h * FO + f], st);
    }
    int idx = h * NN + n;
    g_ssrc[idx] = ss;
    g_stgt[idx] = st;
    g_E1s[idx] = expf(ss);
    g_E2s[idx] = expf(0.2f * ss);
    g_E1t[idx] = expf(st);
    g_E2t[idx] = expf(0.2f * st);
}

// ---------------- split-K fused GAT attention (v4: FFMA2 packed rows) ----------
// Block: 64 i-rows x 256 cols; j-tiles of 32; 2 barriers per tile; 2 CTAs/SM.
// Weight tile stored transposed [h][j][i] so row-pairs load as packed u64.
__global__ void __launch_bounds__(256, 2) attn_split(const float* __restrict__ sw) {
    __shared__ __align__(16) float Psh[32][256];        // 32 KB
    __shared__ __align__(16) float Wts2[4 * PLANE];     // ~35 KB, [h][j][i]
    __shared__ float ss_sh[4][64], E1s_sh[4][64], E2s_sh[4][64];
    __shared__ float Zsh[64][4];

    int t = threadIdx.x;
    int i0 = blockIdx.x * 64;
    int jbase = blockIdx.y * JLEN;

    {
        int h = t >> 6, i = t & 63;
        int idx = h * NN + i0 + i;
        ss_sh[h][i] = g_ssrc[idx];
        E1s_sh[h][i] = g_E1s[idx];
        E2s_sh[h][i] = g_E2s[idx];
        Zsh[t >> 2][t & 3] = 0.f;
    }

    int w = t >> 5, lane = t & 31;
    int r0 = w * 8;            // 8 i-rows per warp (even, 16B-aligned in Wts2)
    int hA = lane >> 4;        // head for cols [cA, cA+4)
    int hB = hA + 2;           // head for cols [128+cA, ...)
    int cA = lane * 4;
    int wi = t >> 2;           // builder: i-row 0..63
    int jj = (t & 3) * 8;      // builder: j offset 0..24
    int prow = t >> 6;         // P loader
    int pcol = (t & 63) * 4;

    const float* swrow = sw + (size_t)(i0 + wi) * NN;
    float4 sw0 = *(const float4*)&swrow[jbase + jj];
    float4 sw1 = *(const float4*)&swrow[jbase + jj + 4];

    float zpart[4] = {0.f, 0.f, 0.f, 0.f};
    u64t accA2[4][4] = {};     // [row-pair][col], packed (r, r+1)
    u64t accB2[4][4] = {};

    for (int j0 = jbase; j0 < jbase + JLEN; j0 += 32) {
        __syncthreads();   // Psh/Wts2 consumable again

        // load P tile (conflict-free float4)
#pragma unroll
        for (int rr = 0; rr < 8; rr++) {
            int row = rr * 4 + prow;
            *(float4*)&Psh[row][pcol] =
                *(const float4*)&g_p[(size_t)(j0 + row) * D2 + pcol];
        }

        // build weight tile into transposed layout Wts2[h][j][i]
#pragma unroll
        for (int h = 0; h < 4; h++) {
            float ssi = ss_sh[h][wi];
            float e1s = E1s_sh[h][wi];
            float e2s = E2s_sh[h][wi];
            int gj = h * NN + j0 + jj;
            float4 st0 = *(const float4*)&g_stgt[gj];
            float4 a0  = *(const float4*)&g_E1t[gj];
            float4 b0  = *(const float4*)&g_E2t[gj];
            float4 st1 = *(const float4*)&g_stgt[gj + 4];
            float4 a1  = *(const float4*)&g_E1t[gj + 4];
            float4 b1  = *(const float4*)&g_E2t[gj + 4];
            float4 w0, w1;
            w0.x = (sw0.x > 0.f) ? ((ssi + st0.x > 0.f) ? e1s * a0.x : e2s * b0.x) : 0.f;
            w0.y = (sw0.y > 0.f) ? ((ssi + st0.y > 0.f) ? e1s * a0.y : e2s * b0.y) : 0.f;
            w0.z = (sw0.z > 0.f) ? ((ssi + st0.z > 0.f) ? e1s * a0.z : e2s * b0.z) : 0.f;
            w0.w = (sw0.w > 0.f) ? ((ssi + st0.w > 0.f) ? e1s * a0.w : e2s * b0.w) : 0.f;
            w1.x = (sw1.x > 0.f) ? ((ssi + st1.x > 0.f) ? e1s * a1.x : e2s * b1.x) : 0.f;
            w1.y = (sw1.y > 0.f) ? ((ssi + st1.y > 0.f) ? e1s * a1.y : e2s * b1.y) : 0.f;
            w1.z = (sw1.z > 0.f) ? ((ssi + st1.z > 0.f) ? e1s * a1.z : e2s * b1.z) : 0.f;
            w1.w = (sw1.w > 0.f) ? ((ssi + st1.w > 0.f) ? e1s * a1.w : e2s * b1.w) : 0.f;
            zpart[h] += ((w0.x + w0.y) + (w0.z + w0.w)) + ((w1.x + w1.y) + (w1.z + w1.w));
            int p = h * PLANE + wi;
            Wts2[p + (jj + 0) * ISTR] = w0.x;
            Wts2[p + (jj + 1) * ISTR] = w0.y;
            Wts2[p + (jj + 2) * ISTR] = w0.z;
            Wts2[p + (jj + 3) * ISTR] = w0.w;
            Wts2[p + (jj + 4) * ISTR] = w1.x;
            Wts2[p + (jj + 5) * ISTR] = w1.y;
            Wts2[p + (jj + 6) * ISTR] = w1.z;
            Wts2[p + (jj + 7) * ISTR] = w1.w;
        }
        __syncthreads();   // tile ready

        // prefetch next tile's sw (hidden under the FMA phase)
        {
            int jn = j0 + 32;
            if (jn >= jbase + JLEN) jn = jbase;   // harmless dummy on last tile
            sw0 = *(const float4*)&swrow[jn + jj];
            sw1 = *(const float4*)&swrow[jn + jj + 4];
        }

        // FFMA2 over the 32-j tile: weights pre-packed over row pairs
#pragma unroll 4
        for (int k = 0; k < 32; k++) {
            {
                float4 pa = *(const float4*)&Psh[k][cA];
                u64t d0 = dup_f2(pa.x), d1 = dup_f2(pa.y);
                u64t d2 = dup_f2(pa.z), d3 = dup_f2(pa.w);
                const float* wb = &Wts2[hA * PLANE + k * ISTR + r0];
                ulonglong2 wv0 = *(const ulonglong2*)wb;       // rows (r0,r0+1),(r0+2,r0+3)
                ulonglong2 wv1 = *(const ulonglong2*)(wb + 4); // rows (r0+4..r0+7)
                fma2(accA2[0][0], wv0.x, d0); fma2(accA2[0][1], wv0.x, d1);
                fma2(accA2[0][2], wv0.x, d2); fma2(accA2[0][3], wv0.x, d3);
                fma2(accA2[1][0], wv0.y, d0); fma2(accA2[1][1], wv0.y, d1);
                fma2(accA2[1][2], wv0.y, d2); fma2(accA2[1][3], wv0.y, d3);
                fma2(accA2[2][0], wv1.x, d0); fma2(accA2[2][1], wv1.x, d1);
                fma2(accA2[2][2], wv1.x, d2); fma2(accA2[2][3], wv1.x, d3);
                fma2(accA2[3][0], wv1.y, d0); fma2(accA2[3][1], wv1.y, d1);
                fma2(accA2[3][2], wv1.y, d2); fma2(accA2[3][3], wv1.y, d3);
            }
            {
                float4 pb = *(const float4*)&Psh[k][128 + cA];
                u64t d0 = dup_f2(pb.x), d1 = dup_f2(pb.y);
                u64t d2 = dup_f2(pb.z), d3 = dup_f2(pb.w);
                const float* wb = &Wts2[hB * PLANE + k * ISTR + r0];
                ulonglong2 wv0 = *(const ulonglong2*)wb;
                ulonglong2 wv1 = *(const ulonglong2*)(wb + 4);
                fma2(accB2[0][0], wv0.x, d0); fma2(accB2[0][1], wv0.x, d1);
                fma2(accB2[0][2], wv0.x, d2); fma2(accB2[0][3], wv0.x, d3);
                fma2(accB2[1][0], wv0.y, d0); fma2(accB2[1][1], wv0.y, d1);
                fma2(accB2[1][2], wv0.y, d2); fma2(accB2[1][3], wv0.y, d3);
                fma2(accB2[2][0], wv1.x, d0); fma2(accB2[2][1], wv1.x, d1);
                fma2(accB2[2][2], wv1.x, d2); fma2(accB2[2][3], wv1.x, d3);
                fma2(accB2[3][0], wv1.y, d0); fma2(accB2[3][1], wv1.y, d1);
                fma2(accB2[3][2], wv1.y, d2); fma2(accB2[3][3], wv1.y, d3);
            }
        }
    }
    __syncthreads();

    // Z reduction
#pragma unroll
    for (int h = 0; h < 4; h++) atomicAdd(&Zsh[wi][h], zpart[h]);
    __syncthreads();
    {
        int i = t >> 2, h = t & 3;
        atomicAdd(&g_Z[h * NN + i0 + i], Zsh[i][h]);
    }
#pragma unroll
    for (int rp = 0; rp < 4; rp++) {
        size_t base = (size_t)(i0 + r0 + 2 * rp) * D2;
#pragma unroll
        for (int c = 0; c < 4; c++) {
            float lo, hi;
            unpack_f2(accA2[rp][c], lo, hi);
            atomicAdd(&g_num[base + cA + c], lo);
            atomicAdd(&g_num[base + D2 + cA + c], hi);
            unpack_f2(accB2[rp][c], lo, hi);
            atomicAdd(&g_num[base + 128 + cA + c], lo);
            atomicAdd(&g_num[base + D2 + 128 + cA + c], hi);
        }
    }
}

// ---------------- finalize: out1 = elu(num/Z + skip + bias1) ----------------
__global__ void attn_finalize(const float* __restrict__ bias1) {
    int t = blockIdx.x * blockDim.x + threadIdx.x;
    if (t >= NN * D2) return;
    int i = t >> 8, c = t & 255;
    int h = c >> 6;
    float v = g_num[t] / g_Z[h * NN + i] + g_skip[t] + bias1[c];
    g_out1[t] = (v > 0.f) ? v : expm1f(v);
}

// ---------------- GATW scores ----------------
__global__ void gatw_scores(const float* __restrict__ a_src2,
                            const float* __restrict__ a_tgt2) {
    int n = blockIdx.x * blockDim.x + threadIdx.x;
    if (n >= NN) return;
    float ss = 0.f, st = 0.f;
    const float* row = g_p2 + (size_t)n * D2;
#pragma unroll 8
    for (int c = 0; c < D2; c++) {
        float v = row[c];
        ss = fmaf(v, a_src2[c], ss);
        st = fmaf(v, a_tgt2[c], st);
    }
    g_ss[n] = ss;
    g_st[n] = st;
}

// ---------------- fused msw + (msw @ W1), v2: attn-style tiles ----------------
// Block: 64 i x 96 c; j-tiles of 32; grid (8 j-splits, 64 i-blocks).
// Warp w owns rows w*8..+7; lane owns cols lane*3..+2 (conflict-free, 3 coprime 32).
__global__ void __launch_bounds__(256) msw_h1(const float* __restrict__ sw,
                                              const float* __restrict__ W1,
                                              float* __restrict__ msw_out) {
    __shared__ __align__(16) float Wm[64][36];     // weight tile [i][j], pad to 36
    __shared__ __align__(16) float W1t[32][96];    // [j][c]
    __shared__ float ss_sh[64];

    int t = threadIdx.x;
    int i0 = blockIdx.y * 64;
    int jbase = blockIdx.x * 512;
    if (t < 64) ss_sh[t] = g_ss[i0 + t];

    int w = t >> 5, lane = t & 31;
    int r0 = w * 8;
    int c0 = lane * 3;
    int wi = t >> 2, jj = (t & 3) * 8;

    const float* swrow = sw + (size_t)(i0 + wi) * NN;
    float acc[8][3] = {};
    __syncthreads();   // ss_sh ready

    for (int j0 = jbase; j0 < jbase + 512; j0 += 32) {
        __syncthreads();
        // stage W1 tile (32 x 96)
#pragma unroll
        for (int e = 0; e < 3; e++) {
            int n = t + e * 256;           // 768 float4s
            int k = n / 24, q = (n % 24) * 4;
            *(float4*)&W1t[k][q] = *(const float4*)&W1[(size_t)(j0 + k) * H1 + q];
        }
        // build weight tile + write msw to output
        {
            float ssi = ss_sh[wi];
            float4 s0 = *(const float4*)&swrow[j0 + jj];
            float4 s1 = *(const float4*)&swrow[j0 + jj + 4];
            float4 t0 = *(const float4*)&g_st[j0 + jj];
            float4 t1 = *(const float4*)&g_st[j0 + jj + 4];
            float4 w0, w1;
            w0.x = fmaxf(ssi + t0.x, 0.f) * s0.x;
            w0.y = fmaxf(ssi + t0.y, 0.f) * s0.y;
            w0.z = fmaxf(ssi + t0.z, 0.f) * s0.z;
            w0.w = fmaxf(ssi + t0.w, 0.f) * s0.w;
            w1.x = fmaxf(ssi + t1.x, 0.f) * s1.x;
            w1.y = fmaxf(ssi + t1.y, 0.f) * s1.y;
            w1.z = fmaxf(ssi + t1.z, 0.f) * s1.z;
            w1.w = fmaxf(ssi + t1.w, 0.f) * s1.w;
            *(float4*)&Wm[wi][jj] = w0;
            *(float4*)&Wm[wi][jj + 4] = w1;
            *(float4*)&msw_out[(size_t)(i0 + wi) * NN + j0 + jj] = w0;
            *(float4*)&msw_out[(size_t)(i0 + wi) * NN + j0 + jj + 4] = w1;
        }
        __syncthreads();

        // FMA: 8 rows x 3 cols per thread over 32 j
        for (int k4 = 0; k4 < 32; k4 += 4) {
            float4 wr[8];
#pragma unroll
            for (int r = 0; r < 8; r++)
                wr[r] = *(const float4*)&Wm[r0 + r][k4];
#pragma unroll
            for (int kk = 0; kk < 4; kk++) {
                float b0 = W1t[k4 + kk][c0];
                float b1 = W1t[k4 + kk][c0 + 1];
                float b2 = W1t[k4 + kk][c0 + 2];
#pragma unroll
                for (int r = 0; r < 8; r++) {
                    float wv = (kk == 0) ? wr[r].x : (kk == 1) ? wr[r].y
                              : (kk == 2) ? wr[r].z : wr[r].w;
                    acc[r][0] = fmaf(wv, b0, acc[r][0]);
                    acc[r][1] = fmaf(wv, b1, acc[r][1]);
                    acc[r][2] = fmaf(wv, b2, acc[r][2]);
                }
            }
        }
    }
#pragma unroll
    for (int r = 0; r < 8; r++)
#pragma unroll
        for (int c = 0; c < 3; c++)
            atomicAdd(&g_h1[(size_t)(i0 + r0 + r) * H1 + c0 + c], acc[r][c]);
}

// ---------------- regression head: h1 -> h2 -> beta, y_hat ----------------
__global__ void __launch_bounds__(256) head_kernel(const float* __restrict__ W2,
                                                   const float* __restrict__ b2,
                                                   const float* __restrict__ W3,
                                                   const float* __restrict__ b3,
                                                   const float* __restrict__ ols,
                                                   const float* __restrict__ vx,
                                                   const float* __restrict__ b1v,
                                                   float* __restrict__ beta_out,
                                                   float* __restrict__ yhat_out) {
    __shared__ float W2s[96][32];
    __shared__ float W3s[32][16];
    __shared__ float b2s[32], b3s[16], olss[16], b1s[96];
    int t = threadIdx.x;
    for (int i = t; i < 96 * 32; i += 256) W2s[i / 32][i % 32] = W2[i];
    for (int i = t; i < 32 * 16; i += 256) W3s[i / 16][i % 16] = W3[i];
    if (t < 32) b2s[t] = b2[t];
    if (t < 16) { b3s[t] = b3[t]; olss[t] = ols[t]; }
    if (t < 96) b1s[t] = b1v[t];
    __syncthreads();

    int n = blockIdx.x * 256 + t;
    if (n >= NN) return;

    float h2[32];
#pragma unroll
    for (int c2 = 0; c2 < 32; c2++) h2[c2] = b2s[c2];
    for (int c = 0; c < 96; c++) {
        float hv = g_h1[(size_t)n * 96 + c] + b1s[c];
#pragma unroll
        for (int c2 = 0; c2 < 32; c2++) h2[c2] = fmaf(hv, W2s[c][c2], h2[c2]);
    }
    float yh = 0.f;
#pragma unroll
    for (int v = 0; v < 16; v++) {
        float s = b3s[v];
#pragma unroll
        for (int c2 = 0; c2 < 32; c2++) s = fmaf(h2[c2], W3s[c2][v], s);
        s = (s > 0.f) ? s : 0.2f * s;
        s *= olss[v];
        beta_out[(size_t)n * 16 + v] = s;
        yh = fmaf(s, vx[(size_t)n * 16 + v], yh);
    }
    yhat_out[n] = yh;
}

// ---------------- launcher (kernel launches ONLY — graph-capture safe) --------
extern "C" void kernel_launch(void* const* d_in, const int* in_sizes, int n_in,
                              void* d_out, int out_size) {
    const float* x    = (const float*)d_in[0];
    const float* sw   = (const float*)d_in[2];
    const float* Wp1  = (const float*)d_in[3];
    const float* a_s1 = (const float*)d_in[4];
    const float* a_t1 = (const float*)d_in[5];
    const float* Wsk  = (const float*)d_in[6];
    const float* bias1= (const float*)d_in[7];
    const float* Wp2  = (const float*)d_in[8];
    const float* a_s2 = (const float*)d_in[9];
    const float* a_t2 = (const float*)d_in[10];
    const float* W1   = (const float*)d_in[11];
    const float* b1   = (const float*)d_in[12];
    const float* W2   = (const float*)d_in[13];
    const float* b2   = (const float*)d_in[14];
    const float* W3   = (const float*)d_in[15];
    const float* b3   = (const float*)d_in[16];
    const float* ols  = (const float*)d_in[17];
    const float* vx   = (const float*)d_in[18];

    float* out = (float*)d_out;
    float* beta_out = out;                       // N*V = 65536
    float* yhat_out = out + NN * VV;             // N = 4096
    float* msw_out  = out + NN * VV + NN;        // N*N

    zero_acc<<<(NN * D2 + 255) / 256, 256>>>();
    xgemm_dual<<<dim3(D2 / 64, NN / 64), 256>>>(x, Wp1, Wsk);
    node_scores<<<(NN * HH + 255) / 256, 256>>>(a_s1, a_t1);
    attn_split<<<dim3(NN / 64, JSPLIT), 256>>>(sw);
    attn_finalize<<<(NN * D2 + 255) / 256, 256>>>(bias1);
    p2gemm<<<dim3(D2 / 64, NN / 64), 256>>>(Wp2);
    gatw_scores<<<NN / 256, 256>>>(a_s2, a_t2);
    msw_h1<<<dim3(8, NN / 64), 256>>>(sw, W1, msw_out);
    head_kernel<<<NN / 256, 256>>>(W2, b2, W3, b3, ols, vx, b1, beta_out, yhat_out);
}